// round 14
// baseline (speedup 1.0000x reference)
#include <cuda_runtime.h>
#include <math.h>

#define NP 262144
#define NR_OI 500
#define SUMH 224
#define SUMW 221
#define SCAT_BLOCKS 256
#define SCAT_THREADS 256
#define CHUNK (NP / SCAT_BLOCKS)    // 1024
#define SCAT2_BLOCKS 512
#define CHUNK2 (NP / SCAT2_BLOCKS)  // 512
#define LOG2E 1.4426950408889634f

typedef unsigned long long ull;

// ---------------- device scratch (no allocations allowed) ----------------
__device__ int            g_bc[SCAT_BLOCKS][512];  // per-block counts -> bases
__device__ int            g_offsets[NR_OI + 1];
__device__ unsigned short g_rank[NP];
__device__ int            g_perm[NP];

__device__ __forceinline__ float ex2f(float a) {
    float r;
    asm("ex2.approx.ftz.f32 %0, %1;" : "=f"(r) : "f"(a));
    return r;
}
__device__ __forceinline__ ull pack2(float lo, float hi) {
    ull r;
    asm("mov.b64 %0, {%1, %2};" : "=l"(r) : "f"(lo), "f"(hi));
    return r;
}
__device__ __forceinline__ void unpack2(ull v, float& lo, float& hi) {
    asm("mov.b64 {%0, %1}, %2;" : "=f"(lo), "=f"(hi) : "l"(v));
}
__device__ __forceinline__ ull fma2(ull a, ull b, ull c) {
    ull r;
    asm("fma.rn.f32x2 %0, %1, %2, %3;" : "=l"(r) : "l"(a), "l"(b), "l"(c));
    return r;
}
__device__ __forceinline__ ull add2(ull a, ull b) {
    ull r;
    asm("add.rn.f32x2 %0, %1, %2;" : "=l"(r) : "l"(a), "l"(b));
    return r;
}

// ---------------- grouping pre-pass (atomic-free global) ----------------
__global__ void __launch_bounds__(SCAT_THREADS)
k_hist(const int* __restrict__ lrix) {
    __shared__ int sc[512];
    for (int t = threadIdx.x; t < 512; t += blockDim.x) sc[t] = 0;
    __syncthreads();
    int base = blockIdx.x * CHUNK;
    for (int j = threadIdx.x; j < CHUNK; j += blockDim.x) {
        int i = base + j;
        int rank = atomicAdd(&sc[lrix[i]], 1);
        g_rank[i] = (unsigned short)rank;
    }
    __syncthreads();
    for (int t = threadIdx.x; t < 512; t += blockDim.x)
        g_bc[blockIdx.x][t] = sc[t];
}

__global__ void __launch_bounds__(512)
k_scan() {
    __shared__ int s[512];
    int t = threadIdx.x;
    int vbuf[16];

    int tot = 0;
    for (int c = 0; c < SCAT_BLOCKS; c += 16) {
#pragma unroll
        for (int u = 0; u < 16; u++) vbuf[u] = g_bc[c + u][t];   // 16 LDG in flight
#pragma unroll
        for (int u = 0; u < 16; u++) tot += vbuf[u];
    }
    s[t] = tot;
    __syncthreads();
    for (int o = 1; o < 512; o <<= 1) {
        int a = (t >= o) ? s[t - o] : 0;
        __syncthreads();
        s[t] += a;
        __syncthreads();
    }
    int excl = s[t] - tot;
    if (t < NR_OI) g_offsets[t] = excl;
    if (t == NR_OI - 1) g_offsets[NR_OI] = s[t];

    int base = excl;
    for (int c = 0; c < SCAT_BLOCKS; c += 16) {
#pragma unroll
        for (int u = 0; u < 16; u++) vbuf[u] = g_bc[c + u][t];   // L2-hot
#pragma unroll
        for (int u = 0; u < 16; u++) {
            g_bc[c + u][t] = base;
            base += vbuf[u];
        }
    }
}

__global__ void __launch_bounds__(SCAT_THREADS)
k_scatter(const int* __restrict__ lrix) {
    __shared__ int sb[512];
    int hb = blockIdx.x >> 1;   // 512 scatter blocks over 256 hist blocks
    for (int t = threadIdx.x; t < 512; t += blockDim.x)
        sb[t] = g_bc[hb][t];
    __syncthreads();
    int base = blockIdx.x * CHUNK2;
    for (int j = threadIdx.x; j < CHUNK2; j += blockDim.x) {
        int i = base + j;
        g_perm[sb[lrix[i]] + (int)g_rank[i]] = i;
    }
}

// ---------------- in-kernel per-region table prep (one warp per level) ----
__device__ __forceinline__ float warp_max(float v) {
#pragma unroll
    for (int o = 16; o; o >>= 1) v = fmaxf(v, __shfl_xor_sync(0xffffffffu, v, o));
    return v;
}
__device__ __forceinline__ float warp_sum(float v) {
#pragma unroll
    for (int o = 16; o; o >>= 1) v += __shfl_xor_sync(0xffffffffu, v, o);
    return v;
}

template <int N, int OH, int OW>
__device__ __forceinline__ void prep_level_w(int lane, int rid,
                                             const float* __restrict__ hemb,
                                             const float* __restrict__ wemb,
                                             float* sLC, float* sLE, float* sCW,
                                             float* sW, float* sWI, float* sB) {
    const int M = N - 1;
    const int J = N / 32;

    float vals[J];
    float mx = -1e30f;
#pragma unroll
    for (int j = 0; j < J; j++) {
        int k = lane + 32 * j;
        vals[j] = (k < M) ? __ldg(&wemb[(size_t)rid * SUMW + OW + k]) : -1e30f;
        mx = fmaxf(mx, vals[j]);
    }
    mx = warp_max(mx);

    float es[J];
    float sum = 0.f;
#pragma unroll
    for (int j = 0; j < J; j++) {
        int k = lane + 32 * j;
        es[j] = (k < M) ? __expf(vals[j] - mx) : 0.f;
        sum += es[j];
    }
    sum = warp_sum(sum);
    float inv = 1.f / sum;

#pragma unroll
    for (int j = 0; j < J; j++) {
        int k = lane + 32 * j;
        float wk = (k < M) ? es[j] * inv : 0.f;
        sW[OH + k] = wk;
        sWI[OH + k] = (wk > 0.f) ? (1.f / wk) : 0.f;
    }
    __syncwarp();

#pragma unroll
    for (int j = 0; j < J; j++) {
        int k = lane + 32 * j;
        float wk = sW[OH + k];
        float wkm1 = (k > 0) ? sW[OH + k - 1] : 0.f;
        float cw = wk + wkm1;
        float le = LOG2E * __ldg(&hemb[(size_t)rid * SUMH + OH + k]);
        sCW[OH + k] = cw;
        sLE[OH + k] = le;
        sLC[OH + k] = le + __log2f(cw);
    }
    __syncwarp();

    // bin locations: per-lane serial over E contiguous, warp scan across lanes
    {
        const int E = N / 32;
        float loc[E];
        float s = 0.f;
#pragma unroll
        for (int m = 0; m < E; m++) {
            loc[m] = s;
            s += sW[OH + E * lane + m];
        }
        float run = s;
#pragma unroll
        for (int o = 1; o < 32; o <<= 1) {
            float nv = __shfl_up_sync(0xffffffffu, run, o);
            if (lane >= o) run += nv;
        }
        float excl = run - s;
#pragma unroll
        for (int m = 0; m < E; m++) {
            int k = E * lane + m;
            sB[OH + k] = (k == 0) ? 0.f : ((k == N - 1) ? 1.f : excl + loc[m]);
        }
    }
}

// ---------------- main per-point kernel ----------------
template <int N, int OFF, int NV>
__device__ __forceinline__ void level_eval(float& xv, float& P, int g, int gsh,
                                           const float4* dv,
                                           const float* __restrict__ sLC,
                                           const float* __restrict__ sLE,
                                           const float* __restrict__ sCW,
                                           const float* __restrict__ sW,
                                           const float* __restrict__ sWI,
                                           const float* __restrict__ sB,
                                           const float* __restrict__ drow) {
    const float* B = sB + OFF;
    const float* LC = sLC + OFF;

    // radix-8 cooperative search: pos = #{k in [1,N-1]: B[k] < xv}
    int pos;
    {
        int step = N / 8;
        int idx = (g + 1) * step;
        if (idx > N - 1) idx = N - 1;
        unsigned b = __ballot_sync(0xffffffffu, B[idx] < xv);
        pos = __popc((b >> gsh) & 0xffu) * step;
    }
    if (N == 128) {
        int idx = pos + (g + 1) * 2;
        if (idx > 127) idx = 127;
        unsigned b = __ballot_sync(0xffffffffu, B[idx] < xv);
        pos += __popc((b >> gsh) & 0xffu) * 2;
        int i2 = pos + 1;
        if (i2 > 127) i2 = 127;
        pos += (B[i2] < xv) ? 1 : 0;
    } else if (N == 64) {
        int idx = pos + (g + 1);
        if (idx > 63) idx = 63;
        unsigned b = __ballot_sync(0xffffffffu, B[idx] < xv);
        pos += __popc((b >> gsh) & 0xffu);
    } else {
        int idx = pos + (g + 1);
        if (idx > 31) idx = 31;
        unsigned b = __ballot_sync(0xffffffffu, B[idx] < xv);
        pos += __popc((b >> gsh) & 0x7u);
    }
    int bin = pos > N - 2 ? N - 2 : pos;

    // hot loop: f32x2-packed FMA/ADD stream, LDS.64 table reads
    const ull L2E2 = pack2(LOG2E, LOG2E);
    ull tot2 = 0ull, part2 = 0ull;   // (0.0f, 0.0f)
#pragma unroll
    for (int i = 0; i < NV; i++) {
        int k = g * 4 + 32 * i;
        float2 l01 = *reinterpret_cast<const float2*>(&LC[k]);
        float2 l23 = *reinterpret_cast<const float2*>(&LC[k + 2]);
        float4 d = dv[i];
        ull e01 = fma2(pack2(d.x, d.y), L2E2, pack2(l01.x, l01.y));
        ull e23 = fma2(pack2(d.z, d.w), L2E2, pack2(l23.x, l23.y));
        float a0, a1, a2, a3;
        unpack2(e01, a0, a1);
        unpack2(e23, a2, a3);
        float t0 = ex2f(a0), t1 = ex2f(a1), t2 = ex2f(a2), t3 = ex2f(a3);
        tot2 = add2(tot2, pack2(t0, t1));
        tot2 = add2(tot2, pack2(t2, t3));
        float p0 = (k < bin) ? t0 : 0.f;
        float p1 = (k + 1 < bin) ? t1 : 0.f;
        float p2 = (k + 2 < bin) ? t2 : 0.f;
        float p3 = (k + 3 < bin) ? t3 : 0.f;
        part2 = add2(part2, pack2(p0, p1));
        part2 = add2(part2, pack2(p2, p3));
    }
    float ta, tb, pa, pb;
    unpack2(tot2, ta, tb);
    unpack2(part2, pa, pb);
    float tot = ta + tb;
    float part = pa + pb;
#pragma unroll
    for (int o = 4; o; o >>= 1) {
        tot += __shfl_xor_sync(0xffffffffu, tot, o);
        part += __shfl_xor_sync(0xffffffffu, part, o);
    }

    // epilogue
    float hl = ex2f(fmaf(__ldg(&drow[OFF + bin]), LOG2E, sLE[OFF + bin]));
    float hr = ex2f(fmaf(__ldg(&drow[OFF + bin + 1]), LOG2E, sLE[OFF + bin + 1]));
    float wb = sW[OFF + bin];
    float wbm1 = sCW[OFF + bin] - wb;
    part = fmaf(hl, wbm1, part);

    float inv_t = __fdividef(1.f, tot);
    float Hl = 2.f * hl * inv_t;
    float dh = 2.f * (hr - hl) * inv_t;
    float alpha = (xv - B[bin]) * sWI[OFF + bin];
    xv = (0.5f * dh * alpha + Hl) * (wb * alpha) + part * inv_t;
    P *= fmaf(alpha, dh, Hl);
}

__global__ void __launch_bounds__(128, 12)
k_main(const float* __restrict__ x,
       const float* __restrict__ delta,
       const int* __restrict__ roi,
       const float* __restrict__ hemb,
       const float* __restrict__ wemb,
       float* __restrict__ out) {
    __shared__ __align__(16) float sLC[SUMH];
    __shared__ float sLE[SUMH];
    __shared__ float sCW[SUMH];
    __shared__ float sW[SUMH];
    __shared__ float sWI[SUMH];
    __shared__ float sB[SUMH];

    int r = blockIdx.x;
    {
        int warp = threadIdx.x >> 5;
        int lane = threadIdx.x & 31;
        int rid = __ldg(&roi[r]);
        if (warp == 0)
            prep_level_w<128, 0, 0>(lane, rid, hemb, wemb, sLC, sLE, sCW, sW, sWI, sB);
        else if (warp == 1)
            prep_level_w<64, 128, 127>(lane, rid, hemb, wemb, sLC, sLE, sCW, sW, sWI, sB);
        else if (warp == 2)
            prep_level_w<32, 192, 190>(lane, rid, hemb, wemb, sLC, sLE, sCW, sW, sWI, sB);
    }
    __syncthreads();

    int g = threadIdx.x & 7;
    int gsh = (threadIdx.x & 31) & 24;
    int grpInBlock = threadIdx.x >> 3;
    int beg = g_offsets[r];
    int end = g_offsets[r + 1];
    int stride = gridDim.y * 16;

    for (int j0 = beg + blockIdx.y * 16; j0 < end; j0 += stride) {
        int j = j0 + grpInBlock;
        bool valid = j < end;
        int jc = valid ? j : end - 1;
        int p = g_perm[jc];
        float xv = __ldg(&x[p]);
        float P = 1.f;
        const float* drow = delta + (size_t)p * SUMH;
        const float4* d4 = reinterpret_cast<const float4*>(drow);

        float4 dv[7];
#pragma unroll
        for (int i = 0; i < 4; i++) dv[i] = __ldg(&d4[g + 8 * i]);
        dv[4] = __ldg(&d4[32 + g]);
        dv[5] = __ldg(&d4[40 + g]);
        dv[6] = __ldg(&d4[48 + g]);

        level_eval<128, 0, 4>(xv, P, g, gsh, dv, sLC, sLE, sCW, sW, sWI, sB, drow);
        level_eval<64, 128, 2>(xv, P, g, gsh, dv + 4, sLC, sLE, sCW, sW, sWI, sB, drow);
        level_eval<32, 192, 1>(xv, P, g, gsh, dv + 6, sLC, sLE, sCW, sW, sWI, sB, drow);

        if (valid && g == 0) {
            out[p] = xv;
            out[NP + p] = __logf(P);
        }
    }
}

// ---------------- launch ----------------
extern "C" void kernel_launch(void* const* d_in, const int* in_sizes, int n_in,
                              void* d_out, int out_size) {
    const float* x     = (const float*)d_in[0];
    const int*   roi   = (const int*)d_in[1];
    const int*   lrix  = (const int*)d_in[2];
    const float* delta = (const float*)d_in[3];
    const float* hemb  = (const float*)d_in[4];
    const float* wemb  = (const float*)d_in[5];
    float* out = (float*)d_out;

    k_hist<<<SCAT_BLOCKS, SCAT_THREADS>>>(lrix);
    k_scan<<<1, 512>>>();
    k_scatter<<<SCAT2_BLOCKS, SCAT_THREADS>>>(lrix);
    k_main<<<dim3(NR_OI, 8), 128>>>(x, delta, roi, hemb, wemb, out);
}

// round 15
// speedup vs baseline: 1.1616x; 1.1616x over previous
#include <cuda_runtime.h>
#include <math.h>

#define NP 262144
#define NR_OI 500
#define SUMH 224
#define SUMW 221
#define SCAT_BLOCKS 128
#define SCAT_THREADS 256
#define CHUNK (NP / SCAT_BLOCKS)    // 2048
#define SCAT2_BLOCKS 512
#define CHUNK2 (NP / SCAT2_BLOCKS)  // 512
#define LOG2E 1.4426950408889634f

typedef unsigned long long ull;

// ---------------- device scratch (no allocations allowed) ----------------
__device__ int            g_bc[SCAT_BLOCKS][512];  // per-block counts -> bases
__device__ int            g_offsets[NR_OI + 1];
__device__ unsigned short g_rank[NP];
__device__ int            g_perm[NP];

__device__ __forceinline__ float ex2f(float a) {
    float r;
    asm("ex2.approx.ftz.f32 %0, %1;" : "=f"(r) : "f"(a));
    return r;
}
__device__ __forceinline__ ull pack2(float lo, float hi) {
    ull r;
    asm("mov.b64 %0, {%1, %2};" : "=l"(r) : "f"(lo), "f"(hi));
    return r;
}
__device__ __forceinline__ void unpack2(ull v, float& lo, float& hi) {
    asm("mov.b64 {%0, %1}, %2;" : "=f"(lo), "=f"(hi) : "l"(v));
}
__device__ __forceinline__ ull fma2(ull a, ull b, ull c) {
    ull r;
    asm("fma.rn.f32x2 %0, %1, %2, %3;" : "=l"(r) : "l"(a), "l"(b), "l"(c));
    return r;
}
__device__ __forceinline__ ull add2(ull a, ull b) {
    ull r;
    asm("add.rn.f32x2 %0, %1, %2;" : "=l"(r) : "l"(a), "l"(b));
    return r;
}

// ---------------- grouping pre-pass (atomic-free global) ----------------
__global__ void __launch_bounds__(SCAT_THREADS)
k_hist(const int* __restrict__ lrix) {
    __shared__ int sc[512];
    for (int t = threadIdx.x; t < 512; t += blockDim.x) sc[t] = 0;
    __syncthreads();
    int base = blockIdx.x * CHUNK;
    const int4* l4 = reinterpret_cast<const int4*>(lrix + base);
    // CHUNK/4 = 512 int4 per block; each thread does 2
    for (int q = threadIdx.x; q < CHUNK / 4; q += blockDim.x) {
        int4 v = l4[q];
        int i = base + q * 4;
        g_rank[i]     = (unsigned short)atomicAdd(&sc[v.x], 1);
        g_rank[i + 1] = (unsigned short)atomicAdd(&sc[v.y], 1);
        g_rank[i + 2] = (unsigned short)atomicAdd(&sc[v.z], 1);
        g_rank[i + 3] = (unsigned short)atomicAdd(&sc[v.w], 1);
    }
    __syncthreads();
    for (int t = threadIdx.x; t < 512; t += blockDim.x)
        g_bc[blockIdx.x][t] = sc[t];
}

__global__ void __launch_bounds__(512)
k_scan() {
    __shared__ int s[512];
    int t = threadIdx.x;
    int vbuf[16];

    int tot = 0;
    for (int c = 0; c < SCAT_BLOCKS; c += 16) {
#pragma unroll
        for (int u = 0; u < 16; u++) vbuf[u] = g_bc[c + u][t];   // 16 LDG in flight
#pragma unroll
        for (int u = 0; u < 16; u++) tot += vbuf[u];
    }
    s[t] = tot;
    __syncthreads();
    for (int o = 1; o < 512; o <<= 1) {
        int a = (t >= o) ? s[t - o] : 0;
        __syncthreads();
        s[t] += a;
        __syncthreads();
    }
    int excl = s[t] - tot;
    if (t < NR_OI) g_offsets[t] = excl;
    if (t == NR_OI - 1) g_offsets[NR_OI] = s[t];

    int base = excl;
    for (int c = 0; c < SCAT_BLOCKS; c += 16) {
#pragma unroll
        for (int u = 0; u < 16; u++) vbuf[u] = g_bc[c + u][t];   // L2-hot
#pragma unroll
        for (int u = 0; u < 16; u++) {
            g_bc[c + u][t] = base;
            base += vbuf[u];
        }
    }
}

__global__ void __launch_bounds__(SCAT_THREADS)
k_scatter(const int* __restrict__ lrix) {
    __shared__ int sb[512];
    int hb = blockIdx.x >> 2;
    for (int t = threadIdx.x; t < 512; t += blockDim.x)
        sb[t] = g_bc[hb][t];
    __syncthreads();
    int base = blockIdx.x * CHUNK2;
    const int4* l4 = reinterpret_cast<const int4*>(lrix + base);
    // CHUNK2/4 = 128 int4 per block; half the threads take one each
    for (int q = threadIdx.x; q < CHUNK2 / 4; q += blockDim.x) {
        int4 v = l4[q];
        int i = base + q * 4;
        ushort4 rk = *reinterpret_cast<const ushort4*>(&g_rank[i]);
        g_perm[sb[v.x] + (int)rk.x] = i;
        g_perm[sb[v.y] + (int)rk.y] = i + 1;
        g_perm[sb[v.z] + (int)rk.z] = i + 2;
        g_perm[sb[v.w] + (int)rk.w] = i + 3;
    }
}

// ---------------- in-kernel per-region table prep (one warp per level) ----
__device__ __forceinline__ float warp_max(float v) {
#pragma unroll
    for (int o = 16; o; o >>= 1) v = fmaxf(v, __shfl_xor_sync(0xffffffffu, v, o));
    return v;
}
__device__ __forceinline__ float warp_sum(float v) {
#pragma unroll
    for (int o = 16; o; o >>= 1) v += __shfl_xor_sync(0xffffffffu, v, o);
    return v;
}

template <int N, int OH, int OW>
__device__ __forceinline__ void prep_level_w(int lane, int rid,
                                             const float* __restrict__ hemb,
                                             const float* __restrict__ wemb,
                                             float* sLC, float* sLE, float* sCW,
                                             float* sW, float* sWI, float* sB) {
    const int M = N - 1;
    const int J = N / 32;

    float vals[J];
    float mx = -1e30f;
#pragma unroll
    for (int j = 0; j < J; j++) {
        int k = lane + 32 * j;
        vals[j] = (k < M) ? __ldg(&wemb[(size_t)rid * SUMW + OW + k]) : -1e30f;
        mx = fmaxf(mx, vals[j]);
    }
    mx = warp_max(mx);

    float es[J];
    float sum = 0.f;
#pragma unroll
    for (int j = 0; j < J; j++) {
        int k = lane + 32 * j;
        es[j] = (k < M) ? __expf(vals[j] - mx) : 0.f;
        sum += es[j];
    }
    sum = warp_sum(sum);
    float inv = 1.f / sum;

#pragma unroll
    for (int j = 0; j < J; j++) {
        int k = lane + 32 * j;
        float wk = (k < M) ? es[j] * inv : 0.f;
        sW[OH + k] = wk;
        sWI[OH + k] = (wk > 0.f) ? (1.f / wk) : 0.f;
    }
    __syncwarp();

#pragma unroll
    for (int j = 0; j < J; j++) {
        int k = lane + 32 * j;
        float wk = sW[OH + k];
        float wkm1 = (k > 0) ? sW[OH + k - 1] : 0.f;
        float cw = wk + wkm1;
        float le = LOG2E * __ldg(&hemb[(size_t)rid * SUMH + OH + k]);
        sCW[OH + k] = cw;
        sLE[OH + k] = le;
        sLC[OH + k] = le + __log2f(cw);
    }
    __syncwarp();

    // bin locations: per-lane serial over E contiguous, warp scan across lanes
    {
        const int E = N / 32;
        float loc[E];
        float s = 0.f;
#pragma unroll
        for (int m = 0; m < E; m++) {
            loc[m] = s;
            s += sW[OH + E * lane + m];
        }
        float run = s;
#pragma unroll
        for (int o = 1; o < 32; o <<= 1) {
            float nv = __shfl_up_sync(0xffffffffu, run, o);
            if (lane >= o) run += nv;
        }
        float excl = run - s;
#pragma unroll
        for (int m = 0; m < E; m++) {
            int k = E * lane + m;
            sB[OH + k] = (k == 0) ? 0.f : ((k == N - 1) ? 1.f : excl + loc[m]);
        }
    }
}

// ---------------- main per-point kernel ----------------
template <int N, int OFF, int NV>
__device__ __forceinline__ void level_eval(float& xv, float& P, int g, int gsh,
                                           const float4* dv,
                                           const float* __restrict__ sLC,
                                           const float* __restrict__ sLE,
                                           const float* __restrict__ sCW,
                                           const float* __restrict__ sW,
                                           const float* __restrict__ sWI,
                                           const float* __restrict__ sB,
                                           const float* __restrict__ drow) {
    const float* B = sB + OFF;
    const float* LC = sLC + OFF;

    // radix-8 cooperative search: pos = #{k in [1,N-1]: B[k] < xv}
    int pos;
    {
        int step = N / 8;
        int idx = (g + 1) * step;
        if (idx > N - 1) idx = N - 1;
        unsigned b = __ballot_sync(0xffffffffu, B[idx] < xv);
        pos = __popc((b >> gsh) & 0xffu) * step;
    }
    if (N == 128) {
        int idx = pos + (g + 1) * 2;
        if (idx > 127) idx = 127;
        unsigned b = __ballot_sync(0xffffffffu, B[idx] < xv);
        pos += __popc((b >> gsh) & 0xffu) * 2;
        int i2 = pos + 1;
        if (i2 > 127) i2 = 127;
        pos += (B[i2] < xv) ? 1 : 0;
    } else if (N == 64) {
        int idx = pos + (g + 1);
        if (idx > 63) idx = 63;
        unsigned b = __ballot_sync(0xffffffffu, B[idx] < xv);
        pos += __popc((b >> gsh) & 0xffu);
    } else {
        int idx = pos + (g + 1);
        if (idx > 31) idx = 31;
        unsigned b = __ballot_sync(0xffffffffu, B[idx] < xv);
        pos += __popc((b >> gsh) & 0x7u);
    }
    int bin = pos > N - 2 ? N - 2 : pos;

    // hot loop: f32x2-packed FMA/ADD stream, LDS.64 table reads
    const ull L2E2 = pack2(LOG2E, LOG2E);
    ull tot2 = 0ull, part2 = 0ull;   // (0.0f, 0.0f)
#pragma unroll
    for (int i = 0; i < NV; i++) {
        int k = g * 4 + 32 * i;
        float2 l01 = *reinterpret_cast<const float2*>(&LC[k]);
        float2 l23 = *reinterpret_cast<const float2*>(&LC[k + 2]);
        float4 d = dv[i];
        ull e01 = fma2(pack2(d.x, d.y), L2E2, pack2(l01.x, l01.y));
        ull e23 = fma2(pack2(d.z, d.w), L2E2, pack2(l23.x, l23.y));
        float a0, a1, a2, a3;
        unpack2(e01, a0, a1);
        unpack2(e23, a2, a3);
        float t0 = ex2f(a0), t1 = ex2f(a1), t2 = ex2f(a2), t3 = ex2f(a3);
        tot2 = add2(tot2, pack2(t0, t1));
        tot2 = add2(tot2, pack2(t2, t3));
        float p0 = (k < bin) ? t0 : 0.f;
        float p1 = (k + 1 < bin) ? t1 : 0.f;
        float p2 = (k + 2 < bin) ? t2 : 0.f;
        float p3 = (k + 3 < bin) ? t3 : 0.f;
        part2 = add2(part2, pack2(p0, p1));
        part2 = add2(part2, pack2(p2, p3));
    }
    float ta, tb, pa, pb;
    unpack2(tot2, ta, tb);
    unpack2(part2, pa, pb);
    float tot = ta + tb;
    float part = pa + pb;
#pragma unroll
    for (int o = 4; o; o >>= 1) {
        tot += __shfl_xor_sync(0xffffffffu, tot, o);
        part += __shfl_xor_sync(0xffffffffu, part, o);
    }

    // epilogue
    float hl = ex2f(fmaf(__ldg(&drow[OFF + bin]), LOG2E, sLE[OFF + bin]));
    float hr = ex2f(fmaf(__ldg(&drow[OFF + bin + 1]), LOG2E, sLE[OFF + bin + 1]));
    float wb = sW[OFF + bin];
    float wbm1 = sCW[OFF + bin] - wb;
    part = fmaf(hl, wbm1, part);

    float inv_t = __fdividef(1.f, tot);
    float Hl = 2.f * hl * inv_t;
    float dh = 2.f * (hr - hl) * inv_t;
    float alpha = (xv - B[bin]) * sWI[OFF + bin];
    xv = (0.5f * dh * alpha + Hl) * (wb * alpha) + part * inv_t;
    P *= fmaf(alpha, dh, Hl);
}

__global__ void __launch_bounds__(128)
k_main(const float* __restrict__ x,
       const float* __restrict__ delta,
       const int* __restrict__ roi,
       const float* __restrict__ hemb,
       const float* __restrict__ wemb,
       float* __restrict__ out) {
    __shared__ __align__(16) float sLC[SUMH];
    __shared__ float sLE[SUMH];
    __shared__ float sCW[SUMH];
    __shared__ float sW[SUMH];
    __shared__ float sWI[SUMH];
    __shared__ float sB[SUMH];

    int r = blockIdx.x;
    {
        int warp = threadIdx.x >> 5;
        int lane = threadIdx.x & 31;
        int rid = __ldg(&roi[r]);
        if (warp == 0)
            prep_level_w<128, 0, 0>(lane, rid, hemb, wemb, sLC, sLE, sCW, sW, sWI, sB);
        else if (warp == 1)
            prep_level_w<64, 128, 127>(lane, rid, hemb, wemb, sLC, sLE, sCW, sW, sWI, sB);
        else if (warp == 2)
            prep_level_w<32, 192, 190>(lane, rid, hemb, wemb, sLC, sLE, sCW, sW, sWI, sB);
    }
    __syncthreads();

    int g = threadIdx.x & 7;
    int gsh = (threadIdx.x & 31) & 24;
    int grpInBlock = threadIdx.x >> 3;
    int beg = g_offsets[r];
    int end = g_offsets[r + 1];
    int stride = gridDim.y * 16;

    for (int j0 = beg + blockIdx.y * 16; j0 < end; j0 += stride) {
        int j = j0 + grpInBlock;
        bool valid = j < end;
        int jc = valid ? j : end - 1;
        int p = g_perm[jc];
        float xv = __ldg(&x[p]);
        float P = 1.f;
        const float* drow = delta + (size_t)p * SUMH;
        const float4* d4 = reinterpret_cast<const float4*>(drow);

        float4 dv[7];
#pragma unroll
        for (int i = 0; i < 4; i++) dv[i] = __ldg(&d4[g + 8 * i]);
        dv[4] = __ldg(&d4[32 + g]);
        dv[5] = __ldg(&d4[40 + g]);
        dv[6] = __ldg(&d4[48 + g]);

        level_eval<128, 0, 4>(xv, P, g, gsh, dv, sLC, sLE, sCW, sW, sWI, sB, drow);
        level_eval<64, 128, 2>(xv, P, g, gsh, dv + 4, sLC, sLE, sCW, sW, sWI, sB, drow);
        level_eval<32, 192, 1>(xv, P, g, gsh, dv + 6, sLC, sLE, sCW, sW, sWI, sB, drow);

        if (valid && g == 0) {
            out[p] = xv;
            out[NP + p] = __logf(P);
        }
    }
}

// ---------------- launch ----------------
extern "C" void kernel_launch(void* const* d_in, const int* in_sizes, int n_in,
                              void* d_out, int out_size) {
    const float* x     = (const float*)d_in[0];
    const int*   roi   = (const int*)d_in[1];
    const int*   lrix  = (const int*)d_in[2];
    const float* delta = (const float*)d_in[3];
    const float* hemb  = (const float*)d_in[4];
    const float* wemb  = (const float*)d_in[5];
    float* out = (float*)d_out;

    k_hist<<<SCAT_BLOCKS, SCAT_THREADS>>>(lrix);
    k_scan<<<1, 512>>>();
    k_scatter<<<SCAT2_BLOCKS, SCAT_THREADS>>>(lrix);
    k_main<<<dim3(NR_OI, 8), 128>>>(x, delta, roi, hemb, wemb, out);
}

// round 16
// speedup vs baseline: 1.2326x; 1.0611x over previous
#include <cuda_runtime.h>
#include <math.h>

#define NP 262144
#define NR_OI 500
#define SUMH 224
#define SUMW 221
#define SCAT_BLOCKS 128
#define SCAT_THREADS 256
#define CHUNK (NP / SCAT_BLOCKS)    // 2048
#define SCAT2_BLOCKS 512
#define CHUNK2 (NP / SCAT2_BLOCKS)  // 512
#define LOG2E 1.4426950408889634f
#define GRIDY 16

typedef unsigned long long ull;

// ---------------- device scratch (no allocations allowed) ----------------
__device__ int            g_bc[SCAT_BLOCKS][512];  // per-block counts -> bases
__device__ int            g_offsets[NR_OI + 1];
__device__ unsigned short g_rank[NP];
__device__ int            g_perm[NP];
// table layout per region: [LC | LE | CW | W | WI | B], each SUMH floats
__device__ __align__(16) float g_tab[NR_OI][6 * SUMH];

__device__ __forceinline__ float ex2f(float a) {
    float r;
    asm("ex2.approx.ftz.f32 %0, %1;" : "=f"(r) : "f"(a));
    return r;
}
__device__ __forceinline__ ull pack2(float lo, float hi) {
    ull r;
    asm("mov.b64 %0, {%1, %2};" : "=l"(r) : "f"(lo), "f"(hi));
    return r;
}
__device__ __forceinline__ void unpack2(ull v, float& lo, float& hi) {
    asm("mov.b64 {%0, %1}, %2;" : "=f"(lo), "=f"(hi) : "l"(v));
}
__device__ __forceinline__ ull fma2(ull a, ull b, ull c) {
    ull r;
    asm("fma.rn.f32x2 %0, %1, %2, %3;" : "=l"(r) : "l"(a), "l"(b), "l"(c));
    return r;
}
__device__ __forceinline__ ull add2(ull a, ull b) {
    ull r;
    asm("add.rn.f32x2 %0, %1, %2;" : "=l"(r) : "l"(a), "l"(b));
    return r;
}

__device__ __forceinline__ float warp_max(float v) {
#pragma unroll
    for (int o = 16; o; o >>= 1) v = fmaxf(v, __shfl_xor_sync(0xffffffffu, v, o));
    return v;
}
__device__ __forceinline__ float warp_sum(float v) {
#pragma unroll
    for (int o = 16; o; o >>= 1) v += __shfl_xor_sync(0xffffffffu, v, o);
    return v;
}

// ---------------- per-region table prep (one warp per level, -> global) ----
template <int N, int OH, int OW>
__device__ __forceinline__ void prep_level_g(int lane, int rid,
                                             const float* __restrict__ hemb,
                                             const float* __restrict__ wemb,
                                             float* sw, float* tab) {
    const int M = N - 1;
    const int J = N / 32;
    float* tLC = tab;
    float* tLE = tab + SUMH;
    float* tCW = tab + 2 * SUMH;
    float* tW  = tab + 3 * SUMH;
    float* tWI = tab + 4 * SUMH;
    float* tB  = tab + 5 * SUMH;

    float vals[J];
    float mx = -1e30f;
#pragma unroll
    for (int j = 0; j < J; j++) {
        int k = lane + 32 * j;
        vals[j] = (k < M) ? __ldg(&wemb[(size_t)rid * SUMW + OW + k]) : -1e30f;
        mx = fmaxf(mx, vals[j]);
    }
    mx = warp_max(mx);

    float es[J];
    float sum = 0.f;
#pragma unroll
    for (int j = 0; j < J; j++) {
        int k = lane + 32 * j;
        es[j] = (k < M) ? __expf(vals[j] - mx) : 0.f;
        sum += es[j];
    }
    sum = warp_sum(sum);
    float inv = 1.f / sum;

#pragma unroll
    for (int j = 0; j < J; j++) {
        int k = lane + 32 * j;
        float wk = (k < M) ? es[j] * inv : 0.f;
        sw[k] = wk;
        tW[OH + k] = wk;
        tWI[OH + k] = (wk > 0.f) ? (1.f / wk) : 0.f;
    }
    __syncwarp();

#pragma unroll
    for (int j = 0; j < J; j++) {
        int k = lane + 32 * j;
        float wk = sw[k];
        float wkm1 = (k > 0) ? sw[k - 1] : 0.f;
        float cw = wk + wkm1;
        float le = LOG2E * __ldg(&hemb[(size_t)rid * SUMH + OH + k]);
        tCW[OH + k] = cw;
        tLE[OH + k] = le;
        tLC[OH + k] = le + __log2f(cw);
    }
    __syncwarp();

    // bin locations: per-lane serial over E contiguous, warp scan across lanes
    {
        const int E = N / 32;
        float loc[E];
        float s = 0.f;
#pragma unroll
        for (int m = 0; m < E; m++) {
            loc[m] = s;
            s += sw[E * lane + m];
        }
        float run = s;
#pragma unroll
        for (int o = 1; o < 32; o <<= 1) {
            float nv = __shfl_up_sync(0xffffffffu, run, o);
            if (lane >= o) run += nv;
        }
        float excl = run - s;
#pragma unroll
        for (int m = 0; m < E; m++) {
            int k = E * lane + m;
            tB[OH + k] = (k == 0) ? 0.f : ((k == N - 1) ? 1.f : excl + loc[m]);
        }
    }
}

// ---------------- fused first node: hist (blocks 0..127) + prep (128..627) --
__global__ void __launch_bounds__(SCAT_THREADS)
k_pre(const int* __restrict__ lrix,
      const int* __restrict__ roi,
      const float* __restrict__ hemb,
      const float* __restrict__ wemb) {
    __shared__ int sc[512];

    if (blockIdx.x >= SCAT_BLOCKS) {
        // ---- table prep for region r ----
        int r = blockIdx.x - SCAT_BLOCKS;
        int warp = threadIdx.x >> 5;
        int lane = threadIdx.x & 31;
        if (warp < 3) {
            int rid = __ldg(&roi[r]);
            float* sw = reinterpret_cast<float*>(sc) + warp * 160;
            float* tab = g_tab[r];
            if (warp == 0)
                prep_level_g<128, 0, 0>(lane, rid, hemb, wemb, sw, tab);
            else if (warp == 1)
                prep_level_g<64, 128, 127>(lane, rid, hemb, wemb, sw, tab);
            else
                prep_level_g<32, 192, 190>(lane, rid, hemb, wemb, sw, tab);
        }
        return;
    }

    // ---- histogram + per-point rank ----
    for (int t = threadIdx.x; t < 512; t += blockDim.x) sc[t] = 0;
    __syncthreads();
    int base = blockIdx.x * CHUNK;
    const int4* l4 = reinterpret_cast<const int4*>(lrix + base);
    for (int q = threadIdx.x; q < CHUNK / 4; q += blockDim.x) {
        int4 v = l4[q];
        int i = base + q * 4;
        g_rank[i]     = (unsigned short)atomicAdd(&sc[v.x], 1);
        g_rank[i + 1] = (unsigned short)atomicAdd(&sc[v.y], 1);
        g_rank[i + 2] = (unsigned short)atomicAdd(&sc[v.z], 1);
        g_rank[i + 3] = (unsigned short)atomicAdd(&sc[v.w], 1);
    }
    __syncthreads();
    for (int t = threadIdx.x; t < 512; t += blockDim.x)
        g_bc[blockIdx.x][t] = sc[t];
}

__global__ void __launch_bounds__(512)
k_scan() {
    __shared__ int s[512];
    int t = threadIdx.x;
    int vbuf[16];

    int tot = 0;
    for (int c = 0; c < SCAT_BLOCKS; c += 16) {
#pragma unroll
        for (int u = 0; u < 16; u++) vbuf[u] = g_bc[c + u][t];   // 16 LDG in flight
#pragma unroll
        for (int u = 0; u < 16; u++) tot += vbuf[u];
    }
    s[t] = tot;
    __syncthreads();
    for (int o = 1; o < 512; o <<= 1) {
        int a = (t >= o) ? s[t - o] : 0;
        __syncthreads();
        s[t] += a;
        __syncthreads();
    }
    int excl = s[t] - tot;
    if (t < NR_OI) g_offsets[t] = excl;
    if (t == NR_OI - 1) g_offsets[NR_OI] = s[t];

    int base = excl;
    for (int c = 0; c < SCAT_BLOCKS; c += 16) {
#pragma unroll
        for (int u = 0; u < 16; u++) vbuf[u] = g_bc[c + u][t];   // L2-hot
#pragma unroll
        for (int u = 0; u < 16; u++) {
            g_bc[c + u][t] = base;
            base += vbuf[u];
        }
    }
}

__global__ void __launch_bounds__(SCAT_THREADS)
k_scatter(const int* __restrict__ lrix) {
    __shared__ int sb[512];
    int hb = blockIdx.x >> 2;
    for (int t = threadIdx.x; t < 512; t += blockDim.x)
        sb[t] = g_bc[hb][t];
    __syncthreads();
    int base = blockIdx.x * CHUNK2;
    const int4* l4 = reinterpret_cast<const int4*>(lrix + base);
    for (int q = threadIdx.x; q < CHUNK2 / 4; q += blockDim.x) {
        int4 v = l4[q];
        int i = base + q * 4;
        ushort4 rk = *reinterpret_cast<const ushort4*>(&g_rank[i]);
        g_perm[sb[v.x] + (int)rk.x] = i;
        g_perm[sb[v.y] + (int)rk.y] = i + 1;
        g_perm[sb[v.z] + (int)rk.z] = i + 2;
        g_perm[sb[v.w] + (int)rk.w] = i + 3;
    }
}

// ---------------- main per-point kernel ----------------
template <int N, int OFF, int NV>
__device__ __forceinline__ void level_eval(float& xv, float& P, int g, int gsh,
                                           const float4* dv,
                                           const float* __restrict__ sLC,
                                           const float* __restrict__ sLE,
                                           const float* __restrict__ sCW,
                                           const float* __restrict__ sW,
                                           const float* __restrict__ sWI,
                                           const float* __restrict__ sB,
                                           const float* __restrict__ drow) {
    const float* B = sB + OFF;
    const float* LC = sLC + OFF;

    // radix-8 cooperative search: pos = #{k in [1,N-1]: B[k] < xv}
    int pos;
    {
        int step = N / 8;
        int idx = (g + 1) * step;
        if (idx > N - 1) idx = N - 1;
        unsigned b = __ballot_sync(0xffffffffu, B[idx] < xv);
        pos = __popc((b >> gsh) & 0xffu) * step;
    }
    if (N == 128) {
        int idx = pos + (g + 1) * 2;
        if (idx > 127) idx = 127;
        unsigned b = __ballot_sync(0xffffffffu, B[idx] < xv);
        pos += __popc((b >> gsh) & 0xffu) * 2;
        int i2 = pos + 1;
        if (i2 > 127) i2 = 127;
        pos += (B[i2] < xv) ? 1 : 0;
    } else if (N == 64) {
        int idx = pos + (g + 1);
        if (idx > 63) idx = 63;
        unsigned b = __ballot_sync(0xffffffffu, B[idx] < xv);
        pos += __popc((b >> gsh) & 0xffu);
    } else {
        int idx = pos + (g + 1);
        if (idx > 31) idx = 31;
        unsigned b = __ballot_sync(0xffffffffu, B[idx] < xv);
        pos += __popc((b >> gsh) & 0x7u);
    }
    int bin = pos > N - 2 ? N - 2 : pos;

    // hot loop: f32x2-packed FMA/ADD stream
    const ull L2E2 = pack2(LOG2E, LOG2E);
    ull tot2 = 0ull, part2 = 0ull;
#pragma unroll
    for (int i = 0; i < NV; i++) {
        int k = g * 4 + 32 * i;
        float2 l01 = *reinterpret_cast<const float2*>(&LC[k]);
        float2 l23 = *reinterpret_cast<const float2*>(&LC[k + 2]);
        float4 d = dv[i];
        ull e01 = fma2(pack2(d.x, d.y), L2E2, pack2(l01.x, l01.y));
        ull e23 = fma2(pack2(d.z, d.w), L2E2, pack2(l23.x, l23.y));
        float a0, a1, a2, a3;
        unpack2(e01, a0, a1);
        unpack2(e23, a2, a3);
        float t0 = ex2f(a0), t1 = ex2f(a1), t2 = ex2f(a2), t3 = ex2f(a3);
        tot2 = add2(tot2, pack2(t0, t1));
        tot2 = add2(tot2, pack2(t2, t3));
        float p0 = (k < bin) ? t0 : 0.f;
        float p1 = (k + 1 < bin) ? t1 : 0.f;
        float p2 = (k + 2 < bin) ? t2 : 0.f;
        float p3 = (k + 3 < bin) ? t3 : 0.f;
        part2 = add2(part2, pack2(p0, p1));
        part2 = add2(part2, pack2(p2, p3));
    }
    float ta, tb, pa, pb;
    unpack2(tot2, ta, tb);
    unpack2(part2, pa, pb);
    float tot = ta + tb;
    float part = pa + pb;
#pragma unroll
    for (int o = 4; o; o >>= 1) {
        tot += __shfl_xor_sync(0xffffffffu, tot, o);
        part += __shfl_xor_sync(0xffffffffu, part, o);
    }

    // epilogue
    float hl = ex2f(fmaf(__ldg(&drow[OFF + bin]), LOG2E, sLE[OFF + bin]));
    float hr = ex2f(fmaf(__ldg(&drow[OFF + bin + 1]), LOG2E, sLE[OFF + bin + 1]));
    float wb = sW[OFF + bin];
    float wbm1 = sCW[OFF + bin] - wb;
    part = fmaf(hl, wbm1, part);

    float inv_t = __fdividef(1.f, tot);
    float Hl = 2.f * hl * inv_t;
    float dh = 2.f * (hr - hl) * inv_t;
    float alpha = (xv - B[bin]) * sWI[OFF + bin];
    xv = (0.5f * dh * alpha + Hl) * (wb * alpha) + part * inv_t;
    P *= fmaf(alpha, dh, Hl);
}

__global__ void __launch_bounds__(128)
k_main(const float* __restrict__ x,
       const float* __restrict__ delta,
       float* __restrict__ out) {
    __shared__ __align__(16) float sT[6 * SUMH];
    const float* sLC = sT;
    const float* sLE = sT + SUMH;
    const float* sCW = sT + 2 * SUMH;
    const float* sW  = sT + 3 * SUMH;
    const float* sWI = sT + 4 * SUMH;
    const float* sB  = sT + 5 * SUMH;

    int r = blockIdx.x;
    {
        const float4* src = reinterpret_cast<const float4*>(g_tab[r]);
        float4* dst = reinterpret_cast<float4*>(sT);
        for (int i = threadIdx.x; i < 6 * SUMH / 4; i += blockDim.x)
            dst[i] = __ldg(&src[i]);
    }
    __syncthreads();

    int g = threadIdx.x & 7;
    int gsh = (threadIdx.x & 31) & 24;
    int grpInBlock = threadIdx.x >> 3;
    int beg = g_offsets[r];
    int end = g_offsets[r + 1];
    int stride = gridDim.y * 16;

    for (int j0 = beg + blockIdx.y * 16; j0 < end; j0 += stride) {
        int j = j0 + grpInBlock;
        bool valid = j < end;
        int jc = valid ? j : end - 1;
        int p = g_perm[jc];
        float xv = __ldg(&x[p]);
        float P = 1.f;
        const float* drow = delta + (size_t)p * SUMH;
        const float4* d4 = reinterpret_cast<const float4*>(drow);

        float4 dv[7];
#pragma unroll
        for (int i = 0; i < 4; i++) dv[i] = __ldg(&d4[g + 8 * i]);
        dv[4] = __ldg(&d4[32 + g]);
        dv[5] = __ldg(&d4[40 + g]);
        dv[6] = __ldg(&d4[48 + g]);

        level_eval<128, 0, 4>(xv, P, g, gsh, dv, sLC, sLE, sCW, sW, sWI, sB, drow);
        level_eval<64, 128, 2>(xv, P, g, gsh, dv + 4, sLC, sLE, sCW, sW, sWI, sB, drow);
        level_eval<32, 192, 1>(xv, P, g, gsh, dv + 6, sLC, sLE, sCW, sW, sWI, sB, drow);

        if (valid && g == 0) {
            out[p] = xv;
            out[NP + p] = __logf(P);
        }
    }
}

// ---------------- launch ----------------
extern "C" void kernel_launch(void* const* d_in, const int* in_sizes, int n_in,
                              void* d_out, int out_size) {
    const float* x     = (const float*)d_in[0];
    const int*   roi   = (const int*)d_in[1];
    const int*   lrix  = (const int*)d_in[2];
    const float* delta = (const float*)d_in[3];
    const float* hemb  = (const float*)d_in[4];
    const float* wemb  = (const float*)d_in[5];
    float* out = (float*)d_out;

    k_pre<<<SCAT_BLOCKS + NR_OI, SCAT_THREADS>>>(lrix, roi, hemb, wemb);
    k_scan<<<1, 512>>>();
    k_scatter<<<SCAT2_BLOCKS, SCAT_THREADS>>>(lrix);
    k_main<<<dim3(NR_OI, GRIDY), 128>>>(x, delta, out);
}